// round 2
// baseline (speedup 1.0000x reference)
#include <cuda_runtime.h>
#include <math.h>

#define N_NODES 100000
#define N_EDGES 3200000
#define N_GRAPHS 64

// ---------------- scratch (device globals: no allocation allowed) ----------
__device__ __align__(16) float g_Z1[N_NODES * 64];    // [n][k(4)][o(16)]
__device__ __align__(16) float g_Z2[N_NODES * 128];   // [n][k(4)][o(32)]
__device__ __align__(16) float g_agg1[N_NODES * 16];  // layer1 accum, then h1 in-place
__device__ __align__(16) float g_agg2[N_NODES * 32];  // layer2 accum, then h2 in-place
__device__ float g_cnt[N_NODES];
__device__ float g_stats1[32];          // sum[16], sumsq[16]
__device__ float g_stats2[64];          // sum[32], sumsq[32]
__device__ float g_bn1[32];             // A[16], B[16]  (h*A+B)
__device__ float g_bn2[64];             // A[32], B[32]
__device__ __align__(16) float g_gsum[N_GRAPHS * 32];
__device__ float g_gcnt[N_GRAPHS];
__device__ int   g_i64;                 // 1 if index inputs are int64

__device__ __forceinline__ void red4(float* p, float4 v) {
    asm volatile("red.global.add.v4.f32 [%0], {%1,%2,%3,%4};"
                 :: "l"(p), "f"(v.x), "f"(v.y), "f"(v.z), "f"(v.w)
                 : "memory");
}

__device__ __forceinline__ float elu1(float v) {
    return v > 0.f ? v : expm1f(v);
}

__device__ __forceinline__ int load_idx(const void* p, long long i, int f64) {
    return f64 ? (int)((const long long*)p)[i] : ((const int*)p)[i];
}

// ---------------- dtype detection: int64 vs int32 indices -------------------
__global__ void k_detect(const int* __restrict__ ei) {
    // If buffer is int64 (values < 2^31), every odd 32-bit word of the first
    // 64 elements is 0. For int32 edge indices those words are random node
    // ids — P(all zero) ~ 0.
    int flag = 1;
    for (int e = 0; e < 64; e++)
        if (ei[2 * e + 1] != 0) { flag = 0; break; }
    g_i64 = flag;
}

// ---------------- Z1 = x @ W1_k  (per node: 3 -> 4x16) ---------------------
__global__ __launch_bounds__(256) void k_z1(const float* __restrict__ x,
                                            const float* __restrict__ W1) {
    __shared__ float sW[192];   // W1[k][i][o] : k*48 + i*16 + o
    __shared__ float sx[64 * 3];
    int t = threadIdx.x;
    if (t < 192) sW[t] = W1[t];
    int base = blockIdx.x * 64;
    if (t < 192) {
        int idx = base * 3 + t;
        sx[t] = (idx < N_NODES * 3) ? x[idx] : 0.f;
    }
    __syncthreads();
    for (int e = t; e < 64 * 64; e += 256) {
        int ln = e >> 6;
        int n = base + ln;
        if (n >= N_NODES) continue;
        int j = e & 63;
        int k = j >> 4, o = j & 15;
        const float* w = sW + k * 48 + o;
        float s = sx[ln * 3 + 0] * w[0] + sx[ln * 3 + 1] * w[16] + sx[ln * 3 + 2] * w[32];
        g_Z1[(size_t)n * 64 + j] = s;
    }
}

// ---------------- layer1 edge scatter --------------------------------------
__global__ __launch_bounds__(256) void k_sc1(const void* __restrict__ ei,
                                             const float* __restrict__ ea) {
    int e = blockIdx.x * blockDim.x + threadIdx.x;
    if (e >= N_EDGES) return;
    int f64 = g_i64;
    int src = load_idx(ei, e, f64);
    int dst = load_idx(ei, (long long)N_EDGES + e, f64);
    float2 pp = ((const float2*)ea)[e];
    float q0 = 1.f - pp.x, q1 = 1.f - pp.y;
    float b0 = q1 * q0, b1 = q1 * pp.x, b2 = pp.y * q0, b3 = pp.y * pp.x;
    const float4* z = (const float4*)(g_Z1 + (size_t)src * 64);
    float* outp = g_agg1 + (size_t)dst * 16;
#pragma unroll
    for (int j = 0; j < 4; j++) {
        float4 a = z[j], b = z[4 + j], c = z[8 + j], d = z[12 + j];
        float4 m;
        m.x = b0 * a.x + b1 * b.x + b2 * c.x + b3 * d.x;
        m.y = b0 * a.y + b1 * b.y + b2 * c.y + b3 * d.y;
        m.z = b0 * a.z + b1 * b.z + b2 * c.z + b3 * d.z;
        m.w = b0 * a.w + b1 * b.w + b2 * c.w + b3 * d.w;
        red4(outp + 4 * j, m);
    }
    atomicAdd(&g_cnt[dst], 1.f);
}

// ---------------- layer1 finalize: mean-div + ELU + BN stats ---------------
__global__ __launch_bounds__(256) void k_fin1() {
    int T = gridDim.x * blockDim.x;          // multiple of 16
    int tid = blockIdx.x * blockDim.x + threadIdx.x;
    float sum = 0.f, sq = 0.f;
    for (int idx = tid; idx < N_NODES * 16; idx += T) {
        int n = idx >> 4;
        float c = fmaxf(g_cnt[n], 1.f);
        float h = elu1(g_agg1[idx] / c);
        g_agg1[idx] = h;
        sum += h; sq += h * h;
    }
    __shared__ float ss[32];
    if (threadIdx.x < 32) ss[threadIdx.x] = 0.f;
    __syncthreads();
    int ch = tid & 15;
    atomicAdd(&ss[ch], sum);
    atomicAdd(&ss[16 + ch], sq);
    __syncthreads();
    if (threadIdx.x < 32) atomicAdd(&g_stats1[threadIdx.x], ss[threadIdx.x]);
}

__global__ void k_bnp1(const float* __restrict__ gam, const float* __restrict__ bet) {
    int i = threadIdx.x;  // < 16
    float mu = g_stats1[i] * (1.f / N_NODES);
    float var = g_stats1[16 + i] * (1.f / N_NODES) - mu * mu;
    float A = rsqrtf(var + 1e-5f) * gam[i];
    g_bn1[i] = A;
    g_bn1[16 + i] = bet[i] - mu * A;
}

// ---------------- Z2 = bn(h1) @ W2_k  (16 -> 4x32) --------------------------
__global__ __launch_bounds__(256) void k_z2(const float* __restrict__ W2) {
    __shared__ float sW[2048];   // W2[k][i][o] : k*512 + i*32 + o
    __shared__ float sh[64 * 16];
    int t = threadIdx.x;
    for (int i = t; i < 2048; i += 256) sW[i] = W2[i];
    int base = blockIdx.x * 64;
    for (int i = t; i < 1024; i += 256) {
        int n = base + (i >> 4);
        int ch = i & 15;
        float h = (n < N_NODES) ? g_agg1[(size_t)n * 16 + ch] : 0.f;
        sh[i] = h * g_bn1[ch] + g_bn1[16 + ch];
    }
    __syncthreads();
    for (int e = t; e < 64 * 128; e += 256) {
        int ln = e >> 7;
        int n = base + ln;
        if (n >= N_NODES) continue;
        int j = e & 127;
        int k = j >> 5, o = j & 31;
        const float* w = sW + k * 512 + o;
        const float* hh = sh + ln * 16;
        float s = 0.f;
#pragma unroll
        for (int i = 0; i < 16; i++) s += hh[i] * w[i * 32];
        g_Z2[(size_t)n * 128 + j] = s;
    }
}

// ---------------- layer2 edge scatter --------------------------------------
__global__ __launch_bounds__(256) void k_sc2(const void* __restrict__ ei,
                                             const float* __restrict__ ea) {
    int e = blockIdx.x * blockDim.x + threadIdx.x;
    if (e >= N_EDGES) return;
    int f64 = g_i64;
    int src = load_idx(ei, e, f64);
    int dst = load_idx(ei, (long long)N_EDGES + e, f64);
    float2 pp = ((const float2*)ea)[e];
    float q0 = 1.f - pp.x, q1 = 1.f - pp.y;
    float b0 = q1 * q0, b1 = q1 * pp.x, b2 = pp.y * q0, b3 = pp.y * pp.x;
    const float4* z = (const float4*)(g_Z2 + (size_t)src * 128);
    float* outp = g_agg2 + (size_t)dst * 32;
#pragma unroll
    for (int j = 0; j < 8; j++) {
        float4 a = z[j], b = z[8 + j], c = z[16 + j], d = z[24 + j];
        float4 m;
        m.x = b0 * a.x + b1 * b.x + b2 * c.x + b3 * d.x;
        m.y = b0 * a.y + b1 * b.y + b2 * c.y + b3 * d.y;
        m.z = b0 * a.z + b1 * b.z + b2 * c.z + b3 * d.z;
        m.w = b0 * a.w + b1 * b.w + b2 * c.w + b3 * d.w;
        red4(outp + 4 * j, m);
    }
}

// ---------------- layer2 finalize ------------------------------------------
__global__ __launch_bounds__(256) void k_fin2() {
    int T = gridDim.x * blockDim.x;          // multiple of 32
    int tid = blockIdx.x * blockDim.x + threadIdx.x;
    float sum = 0.f, sq = 0.f;
    for (int idx = tid; idx < N_NODES * 32; idx += T) {
        int n = idx >> 5;
        float c = fmaxf(g_cnt[n], 1.f);
        float h = elu1(g_agg2[idx] / c);
        g_agg2[idx] = h;
        sum += h; sq += h * h;
    }
    __shared__ float ss[64];
    if (threadIdx.x < 64) ss[threadIdx.x] = 0.f;
    __syncthreads();
    int ch = tid & 31;
    atomicAdd(&ss[ch], sum);
    atomicAdd(&ss[32 + ch], sq);
    __syncthreads();
    if (threadIdx.x < 64) atomicAdd(&g_stats2[threadIdx.x], ss[threadIdx.x]);
}

__global__ void k_bnp2(const float* __restrict__ gam, const float* __restrict__ bet) {
    int i = threadIdx.x;  // < 32
    float mu = g_stats2[i] * (1.f / N_NODES);
    float var = g_stats2[32 + i] * (1.f / N_NODES) - mu * mu;
    float A = rsqrtf(var + 1e-5f) * gam[i];
    g_bn2[i] = A;
    g_bn2[32 + i] = bet[i] - mu * A;
}

// ---------------- graph mean pool (batch is sorted) -------------------------
__global__ __launch_bounds__(256) void k_pool(const void* __restrict__ batch) {
    __shared__ float sg[N_GRAPHS * 32];
    __shared__ float sc[N_GRAPHS];
    int t = threadIdx.x;
    for (int i = t; i < N_GRAPHS * 32; i += 256) sg[i] = 0.f;
    if (t < N_GRAPHS) sc[t] = 0.f;
    __syncthreads();
    int f64 = g_i64;
    int lane = t & 31, warp = t >> 5;
    const int NPW = 256;
    int gw = blockIdx.x * 8 + warp;
    int start = gw * NPW;
    int end = min(start + NPW, N_NODES);
    float A = g_bn2[lane], B = g_bn2[32 + lane];
    float acc = 0.f, cacc = 0.f;
    int curg = -1;
    for (int n = start; n < end; n++) {
        int g = load_idx(batch, n, f64);
        if (g != curg) {
            if (curg >= 0) {
                atomicAdd(&sg[curg * 32 + lane], acc);
                if (lane == 0) atomicAdd(&sc[curg], cacc);
            }
            curg = g; acc = 0.f; cacc = 0.f;
        }
        float h = g_agg2[(size_t)n * 32 + lane];
        acc += h * A + B;
        cacc += 1.f;
    }
    if (curg >= 0) {
        atomicAdd(&sg[curg * 32 + lane], acc);
        if (lane == 0) atomicAdd(&sc[curg], cacc);
    }
    __syncthreads();
    for (int i = t; i < N_GRAPHS * 32; i += 256)
        if (sg[i] != 0.f) atomicAdd(&g_gsum[i], sg[i]);
    if (t < N_GRAPHS && sc[t] != 0.f) atomicAdd(&g_gcnt[t], sc[t]);
}

// ---------------- final: gm @ fc_w^T ----------------------------------------
__global__ void k_final(const float* __restrict__ fc, float* __restrict__ out) {
    int t = threadIdx.x;
    if (t >= N_GRAPHS * 10) return;
    int g = t / 10, c = t % 10;
    float cg = fmaxf(g_gcnt[g], 1.f);
    float inv = 1.f / cg;
    float s = 0.f;
#pragma unroll
    for (int i = 0; i < 32; i++) s += (g_gsum[g * 32 + i] * inv) * fc[c * 32 + i];
    out[g * 10 + c] = s;
}

// ---------------- launch -----------------------------------------------------
extern "C" void kernel_launch(void* const* d_in, const int* in_sizes, int n_in,
                              void* d_out, int out_size) {
    const float* x     = (const float*)d_in[0];
    const void*  ei    = d_in[1];
    const float* ea    = (const float*)d_in[2];
    const void*  batch = d_in[3];
    const float* W1    = (const float*)d_in[4];
    const float* g1    = (const float*)d_in[5];
    const float* b1    = (const float*)d_in[6];
    const float* W2    = (const float*)d_in[7];
    const float* g2    = (const float*)d_in[8];
    const float* b2    = (const float*)d_in[9];
    const float* fc    = (const float*)d_in[10];
    float* out = (float*)d_out;

    void* p;
    cudaGetSymbolAddress(&p, g_agg1);   cudaMemsetAsync(p, 0, sizeof(g_agg1));
    cudaGetSymbolAddress(&p, g_agg2);   cudaMemsetAsync(p, 0, sizeof(g_agg2));
    cudaGetSymbolAddress(&p, g_cnt);    cudaMemsetAsync(p, 0, sizeof(g_cnt));
    cudaGetSymbolAddress(&p, g_stats1); cudaMemsetAsync(p, 0, sizeof(g_stats1));
    cudaGetSymbolAddress(&p, g_stats2); cudaMemsetAsync(p, 0, sizeof(g_stats2));
    cudaGetSymbolAddress(&p, g_gsum);   cudaMemsetAsync(p, 0, sizeof(g_gsum));
    cudaGetSymbolAddress(&p, g_gcnt);   cudaMemsetAsync(p, 0, sizeof(g_gcnt));

    int nodeBlocks = (N_NODES + 63) / 64;
    int edgeBlocks = (N_EDGES + 255) / 256;

    k_detect<<<1, 1>>>((const int*)ei);
    k_z1<<<nodeBlocks, 256>>>(x, W1);
    k_sc1<<<edgeBlocks, 256>>>(ei, ea);
    k_fin1<<<592, 256>>>();
    k_bnp1<<<1, 16>>>(g1, b1);
    k_z2<<<nodeBlocks, 256>>>(W2);
    k_sc2<<<edgeBlocks, 256>>>(ei, ea);
    k_fin2<<<592, 256>>>();
    k_bnp2<<<1, 32>>>(g2, b2);
    k_pool<<<(N_NODES + 8 * 256 - 1) / (8 * 256), 256>>>(batch);
    k_final<<<1, N_GRAPHS * 10>>>(fc, out);
}

// round 3
// speedup vs baseline: 1.3868x; 1.3868x over previous
#include <cuda_runtime.h>
#include <cuda_fp16.h>
#include <math.h>

#define N_NODES 100000
#define N_EDGES 3200000
#define N_GRAPHS 64

// ---------------- scratch (device globals: no allocation allowed) ----------
__device__ __align__(16) __half g_Z1h[N_NODES * 64];    // [n][k(4)][o(16)] fp16
__device__ __align__(16) __half g_Z2h[N_NODES * 128];   // [n][k(4)][o(32)] fp16
__device__ __align__(16) uint4  g_erec[N_EDGES];        // {src, dst, b01, b23}
__device__ __align__(16) float g_agg1[N_NODES * 16];
__device__ __align__(16) float g_agg2[N_NODES * 32];
__device__ float g_cnt[N_NODES];
__device__ float g_stats1[32];          // sum[16], sumsq[16]
__device__ float g_stats2[64];          // sum[32], sumsq[32]
__device__ float g_bn1[32];             // A[16], B[16]  (h*A+B)
__device__ float g_bn2[64];             // A[32], B[32]
__device__ __align__(16) float g_gsum[N_GRAPHS * 32];
__device__ float g_gcnt[N_GRAPHS];
__device__ int   g_i64;                 // 1 if index inputs are int64

__device__ __forceinline__ void red4(float* p, float4 v) {
    asm volatile("red.global.add.v4.f32 [%0], {%1,%2,%3,%4};"
                 :: "l"(p), "f"(v.x), "f"(v.y), "f"(v.z), "f"(v.w)
                 : "memory");
}

__device__ __forceinline__ float elu1(float v) {
    return v > 0.f ? v : expm1f(v);
}

__device__ __forceinline__ int load_idx(const void* p, long long i, int f64) {
    return f64 ? (int)((const long long*)p)[i] : ((const int*)p)[i];
}

// extract 4 consecutive halfs (quad q-half: hi=0 -> .x/.y, hi=1 -> .z/.w) as float4
__device__ __forceinline__ float4 h8_quad(uint4 v, int hi) {
    unsigned a = hi ? v.z : v.x;
    unsigned b = hi ? v.w : v.y;
    __half2 ha = *reinterpret_cast<__half2*>(&a);
    __half2 hb = *reinterpret_cast<__half2*>(&b);
    float2 f0 = __half22float2(ha), f1 = __half22float2(hb);
    return make_float4(f0.x, f0.y, f1.x, f1.y);
}

// ---------------- dtype detection: int64 vs int32 indices -------------------
__global__ void k_detect(const int* __restrict__ ei) {
    int flag = 1;
    for (int e = 0; e < 64; e++)
        if (ei[2 * e + 1] != 0) { flag = 0; break; }
    g_i64 = flag;
}

// ---------------- edge preprocess: pack rec + degree count ------------------
__global__ __launch_bounds__(256) void k_prep(const void* __restrict__ ei,
                                              const float* __restrict__ ea) {
    int e = blockIdx.x * blockDim.x + threadIdx.x;
    if (e >= N_EDGES) return;
    int f64 = g_i64;
    int src = load_idx(ei, e, f64);
    int dst = load_idx(ei, (long long)N_EDGES + e, f64);
    float2 pp = ((const float2*)ea)[e];
    float q0 = 1.f - pp.x, q1 = 1.f - pp.y;
    float b0 = q1 * q0, b1 = q1 * pp.x, b2 = pp.y * q0, b3 = pp.y * pp.x;
    __half2 h01 = __floats2half2_rn(b0, b1);
    __half2 h23 = __floats2half2_rn(b2, b3);
    uint4 r;
    r.x = (unsigned)src;
    r.y = (unsigned)dst;
    r.z = *reinterpret_cast<unsigned*>(&h01);
    r.w = *reinterpret_cast<unsigned*>(&h23);
    g_erec[e] = r;
    atomicAdd(&g_cnt[dst], 1.f);
}

// ---------------- Z1 = x @ W1_k  (per node: 3 -> 4x16, fp16 out) -----------
__global__ __launch_bounds__(256) void k_z1(const float* __restrict__ x,
                                            const float* __restrict__ W1) {
    __shared__ float sW[192];   // W1[k][i][o] : k*48 + i*16 + o
    __shared__ float sx[64 * 3];
    int t = threadIdx.x;
    if (t < 192) sW[t] = W1[t];
    int base = blockIdx.x * 64;
    if (t < 192) {
        int idx = base * 3 + t;
        sx[t] = (idx < N_NODES * 3) ? x[idx] : 0.f;
    }
    __syncthreads();
    for (int e = t; e < 64 * 64; e += 256) {
        int ln = e >> 6;
        int n = base + ln;
        if (n >= N_NODES) continue;
        int j = e & 63;
        int k = j >> 4, o = j & 15;
        const float* w = sW + k * 48 + o;
        float s = sx[ln * 3 + 0] * w[0] + sx[ln * 3 + 1] * w[16] + sx[ln * 3 + 2] * w[32];
        g_Z1h[(size_t)n * 64 + j] = __float2half(s);
    }
}

// ---------------- layer1 edge scatter (fp16 gather) -------------------------
__global__ __launch_bounds__(256) void k_sc1() {
    int e = blockIdx.x * blockDim.x + threadIdx.x;
    if (e >= N_EDGES) return;
    uint4 r = g_erec[e];
    int src = (int)r.x, dst = (int)r.y;
    __half2 h01 = *reinterpret_cast<__half2*>(&r.z);
    __half2 h23 = *reinterpret_cast<__half2*>(&r.w);
    float2 f01 = __half22float2(h01), f23 = __half22float2(h23);
    float bb[4] = {f01.x, f01.y, f23.x, f23.y};
    const uint4* zp = (const uint4*)(g_Z1h + (size_t)src * 64);  // 8 x uint4
    uint4 zr[8];
#pragma unroll
    for (int i = 0; i < 8; i++) zr[i] = zp[i];
    float* outp = g_agg1 + (size_t)dst * 16;
#pragma unroll
    for (int q = 0; q < 4; q++) {
        float4 m = make_float4(0.f, 0.f, 0.f, 0.f);
#pragma unroll
        for (int k = 0; k < 4; k++) {
            float4 zq = h8_quad(zr[k * 2 + (q >> 1)], q & 1);
            m.x += bb[k] * zq.x; m.y += bb[k] * zq.y;
            m.z += bb[k] * zq.z; m.w += bb[k] * zq.w;
        }
        red4(outp + 4 * q, m);
    }
}

// ---------------- layer1 finalize: mean-div + ELU + BN stats ---------------
__global__ __launch_bounds__(256) void k_fin1() {
    int T = gridDim.x * blockDim.x;
    int tid = blockIdx.x * blockDim.x + threadIdx.x;
    float sum = 0.f, sq = 0.f;
    for (int idx = tid; idx < N_NODES * 16; idx += T) {
        int n = idx >> 4;
        float c = fmaxf(g_cnt[n], 1.f);
        float h = elu1(g_agg1[idx] / c);
        g_agg1[idx] = h;
        sum += h; sq += h * h;
    }
    __shared__ float ss[32];
    if (threadIdx.x < 32) ss[threadIdx.x] = 0.f;
    __syncthreads();
    int ch = tid & 15;
    atomicAdd(&ss[ch], sum);
    atomicAdd(&ss[16 + ch], sq);
    __syncthreads();
    if (threadIdx.x < 32) atomicAdd(&g_stats1[threadIdx.x], ss[threadIdx.x]);
}

__global__ void k_bnp1(const float* __restrict__ gam, const float* __restrict__ bet) {
    int i = threadIdx.x;  // < 16
    float mu = g_stats1[i] * (1.f / N_NODES);
    float var = g_stats1[16 + i] * (1.f / N_NODES) - mu * mu;
    float A = rsqrtf(var + 1e-5f) * gam[i];
    g_bn1[i] = A;
    g_bn1[16 + i] = bet[i] - mu * A;
}

// ---------------- Z2 = bn(h1) @ W2_k  (16 -> 4x32, fp16 out) ----------------
__global__ __launch_bounds__(256) void k_z2(const float* __restrict__ W2) {
    __shared__ float sW[2048];   // W2[k][i][o] : k*512 + i*32 + o
    __shared__ float sh[64 * 16];
    int t = threadIdx.x;
    for (int i = t; i < 2048; i += 256) sW[i] = W2[i];
    int base = blockIdx.x * 64;
    for (int i = t; i < 1024; i += 256) {
        int n = base + (i >> 4);
        int ch = i & 15;
        float h = (n < N_NODES) ? g_agg1[(size_t)n * 16 + ch] : 0.f;
        sh[i] = h * g_bn1[ch] + g_bn1[16 + ch];
    }
    __syncthreads();
    for (int e = t; e < 64 * 128; e += 256) {
        int ln = e >> 7;
        int n = base + ln;
        if (n >= N_NODES) continue;
        int j = e & 127;
        int k = j >> 5, o = j & 31;
        const float* w = sW + k * 512 + o;
        const float* hh = sh + ln * 16;
        float s = 0.f;
#pragma unroll
        for (int i = 0; i < 16; i++) s += hh[i] * w[i * 32];
        g_Z2h[(size_t)n * 128 + j] = __float2half(s);
    }
}

// ---------------- layer2 edge scatter (fp16 gather) -------------------------
__global__ __launch_bounds__(128) void k_sc2() {
    int e = blockIdx.x * blockDim.x + threadIdx.x;
    if (e >= N_EDGES) return;
    uint4 r = g_erec[e];
    int src = (int)r.x, dst = (int)r.y;
    __half2 h01 = *reinterpret_cast<__half2*>(&r.z);
    __half2 h23 = *reinterpret_cast<__half2*>(&r.w);
    float2 f01 = __half22float2(h01), f23 = __half22float2(h23);
    float bb[4] = {f01.x, f01.y, f23.x, f23.y};
    const uint4* zp = (const uint4*)(g_Z2h + (size_t)src * 128);  // 16 x uint4
    uint4 zr[16];
#pragma unroll
    for (int i = 0; i < 16; i++) zr[i] = zp[i];
    float* outp = g_agg2 + (size_t)dst * 32;
#pragma unroll
    for (int q = 0; q < 8; q++) {
        float4 m = make_float4(0.f, 0.f, 0.f, 0.f);
#pragma unroll
        for (int k = 0; k < 4; k++) {
            float4 zq = h8_quad(zr[k * 4 + (q >> 1)], q & 1);
            m.x += bb[k] * zq.x; m.y += bb[k] * zq.y;
            m.z += bb[k] * zq.z; m.w += bb[k] * zq.w;
        }
        red4(outp + 4 * q, m);
    }
}

// ---------------- layer2 finalize ------------------------------------------
__global__ __launch_bounds__(256) void k_fin2() {
    int T = gridDim.x * blockDim.x;
    int tid = blockIdx.x * blockDim.x + threadIdx.x;
    float sum = 0.f, sq = 0.f;
    for (int idx = tid; idx < N_NODES * 32; idx += T) {
        int n = idx >> 5;
        float c = fmaxf(g_cnt[n], 1.f);
        float h = elu1(g_agg2[idx] / c);
        g_agg2[idx] = h;
        sum += h; sq += h * h;
    }
    __shared__ float ss[64];
    if (threadIdx.x < 64) ss[threadIdx.x] = 0.f;
    __syncthreads();
    int ch = tid & 31;
    atomicAdd(&ss[ch], sum);
    atomicAdd(&ss[32 + ch], sq);
    __syncthreads();
    if (threadIdx.x < 64) atomicAdd(&g_stats2[threadIdx.x], ss[threadIdx.x]);
}

__global__ void k_bnp2(const float* __restrict__ gam, const float* __restrict__ bet) {
    int i = threadIdx.x;  // < 32
    float mu = g_stats2[i] * (1.f / N_NODES);
    float var = g_stats2[32 + i] * (1.f / N_NODES) - mu * mu;
    float A = rsqrtf(var + 1e-5f) * gam[i];
    g_bn2[i] = A;
    g_bn2[32 + i] = bet[i] - mu * A;
}

// ---------------- graph mean pool (batch is sorted) -------------------------
__global__ __launch_bounds__(256) void k_pool(const void* __restrict__ batch) {
    __shared__ float sg[N_GRAPHS * 32];
    __shared__ float sc[N_GRAPHS];
    int t = threadIdx.x;
    for (int i = t; i < N_GRAPHS * 32; i += 256) sg[i] = 0.f;
    if (t < N_GRAPHS) sc[t] = 0.f;
    __syncthreads();
    int f64 = g_i64;
    int lane = t & 31, warp = t >> 5;
    const int NPW = 256;
    int gw = blockIdx.x * 8 + warp;
    int start = gw * NPW;
    int end = min(start + NPW, N_NODES);
    float A = g_bn2[lane], B = g_bn2[32 + lane];
    float acc = 0.f, cacc = 0.f;
    int curg = -1;
    for (int n = start; n < end; n++) {
        int g = load_idx(batch, n, f64);
        if (g != curg) {
            if (curg >= 0) {
                atomicAdd(&sg[curg * 32 + lane], acc);
                if (lane == 0) atomicAdd(&sc[curg], cacc);
            }
            curg = g; acc = 0.f; cacc = 0.f;
        }
        float h = g_agg2[(size_t)n * 32 + lane];
        acc += h * A + B;
        cacc += 1.f;
    }
    if (curg >= 0) {
        atomicAdd(&sg[curg * 32 + lane], acc);
        if (lane == 0) atomicAdd(&sc[curg], cacc);
    }
    __syncthreads();
    for (int i = t; i < N_GRAPHS * 32; i += 256)
        if (sg[i] != 0.f) atomicAdd(&g_gsum[i], sg[i]);
    if (t < N_GRAPHS && sc[t] != 0.f) atomicAdd(&g_gcnt[t], sc[t]);
}

// ---------------- final: gm @ fc_w^T ----------------------------------------
__global__ void k_final(const float* __restrict__ fc, float* __restrict__ out) {
    int t = threadIdx.x;
    if (t >= N_GRAPHS * 10) return;
    int g = t / 10, c = t % 10;
    float cg = fmaxf(g_gcnt[g], 1.f);
    float inv = 1.f / cg;
    float s = 0.f;
#pragma unroll
    for (int i = 0; i < 32; i++) s += (g_gsum[g * 32 + i] * inv) * fc[c * 32 + i];
    out[g * 10 + c] = s;
}

// ---------------- launch -----------------------------------------------------
extern "C" void kernel_launch(void* const* d_in, const int* in_sizes, int n_in,
                              void* d_out, int out_size) {
    const float* x     = (const float*)d_in[0];
    const void*  ei    = d_in[1];
    const float* ea    = (const float*)d_in[2];
    const void*  batch = d_in[3];
    const float* W1    = (const float*)d_in[4];
    const float* g1    = (const float*)d_in[5];
    const float* b1    = (const float*)d_in[6];
    const float* W2    = (const float*)d_in[7];
    const float* g2    = (const float*)d_in[8];
    const float* b2    = (const float*)d_in[9];
    const float* fc    = (const float*)d_in[10];
    float* out = (float*)d_out;

    void* p;
    cudaGetSymbolAddress(&p, g_agg1);   cudaMemsetAsync(p, 0, sizeof(g_agg1));
    cudaGetSymbolAddress(&p, g_agg2);   cudaMemsetAsync(p, 0, sizeof(g_agg2));
    cudaGetSymbolAddress(&p, g_cnt);    cudaMemsetAsync(p, 0, sizeof(g_cnt));
    cudaGetSymbolAddress(&p, g_stats1); cudaMemsetAsync(p, 0, sizeof(g_stats1));
    cudaGetSymbolAddress(&p, g_stats2); cudaMemsetAsync(p, 0, sizeof(g_stats2));
    cudaGetSymbolAddress(&p, g_gsum);   cudaMemsetAsync(p, 0, sizeof(g_gsum));
    cudaGetSymbolAddress(&p, g_gcnt);   cudaMemsetAsync(p, 0, sizeof(g_gcnt));

    int nodeBlocks = (N_NODES + 63) / 64;

    k_detect<<<1, 1>>>((const int*)ei);
    k_prep<<<(N_EDGES + 255) / 256, 256>>>(ei, ea);
    k_z1<<<nodeBlocks, 256>>>(x, W1);
    k_sc1<<<(N_EDGES + 255) / 256, 256>>>();
    k_fin1<<<592, 256>>>();
    k_bnp1<<<1, 16>>>(g1, b1);
    k_z2<<<nodeBlocks, 256>>>(W2);
    k_sc2<<<(N_EDGES + 127) / 128, 128>>>();
    k_fin2<<<592, 256>>>();
    k_bnp2<<<1, 32>>>(g2, b2);
    k_pool<<<(N_NODES + 8 * 256 - 1) / (8 * 256), 256>>>(batch);
    k_final<<<1, N_GRAPHS * 10>>>(fc, out);
}

// round 4
// speedup vs baseline: 2.3315x; 1.6812x over previous
#include <cuda_runtime.h>
#include <cuda_fp16.h>
#include <math.h>

#define N_NODES 100000
#define N_EDGES 3200000
#define N_GRAPHS 64

// ---------------- scratch (device globals: no allocation allowed) ----------
__device__ __align__(16) __half g_Z1h[N_NODES * 64];    // [n][k(4)][o(16)] fp16
__device__ __align__(16) __half g_Z2h[N_NODES * 128];   // [n][k(4)][o(32)] fp16
__device__ __align__(16) uint4  g_erec[N_EDGES];        // {src, dst, p0(f32), p1(f32)}
__device__ __align__(16) float g_agg1[N_NODES * 16];
__device__ __align__(16) float g_agg2[N_NODES * 32];
__device__ float g_cnt[N_NODES];
__device__ float g_stats1[32];          // sum[16], sumsq[16]
__device__ float g_stats2[64];          // sum[32], sumsq[32]
__device__ float g_bn1[32];             // A[16], B[16]  (h*A+B)
__device__ float g_bn2[64];             // A[32], B[32]
__device__ __align__(16) float g_gsum[N_GRAPHS * 32];
__device__ float g_gcnt[N_GRAPHS];
__device__ int   g_i64;                 // 1 if index inputs are int64

__device__ __forceinline__ void red4(float* p, float4 v) {
    asm volatile("red.global.add.v4.f32 [%0], {%1,%2,%3,%4};"
                 :: "l"(p), "f"(v.x), "f"(v.y), "f"(v.z), "f"(v.w)
                 : "memory");
}

__device__ __forceinline__ float elu1(float v) {
    return v > 0.f ? v : expm1f(v);
}

__device__ __forceinline__ int load_idx(const void* p, long long i, int f64) {
    return f64 ? (int)((const long long*)p)[i] : ((const int*)p)[i];
}

// 4 consecutive halfs (uint2) -> float4
__device__ __forceinline__ float4 h4f(uint2 v) {
    __half2 a = *reinterpret_cast<__half2*>(&v.x);
    __half2 b = *reinterpret_cast<__half2*>(&v.y);
    float2 f0 = __half22float2(a), f1 = __half22float2(b);
    return make_float4(f0.x, f0.y, f1.x, f1.y);
}

// ---------------- dtype detection: int64 vs int32 indices -------------------
__global__ void k_detect(const int* __restrict__ ei) {
    int flag = 1;
    for (int e = 0; e < 64; e++)
        if (ei[2 * e + 1] != 0) { flag = 0; break; }
    g_i64 = flag;
}

// ---------------- edge preprocess: pack rec + degree count ------------------
__global__ __launch_bounds__(256) void k_prep(const void* __restrict__ ei,
                                              const float* __restrict__ ea) {
    int e = blockIdx.x * blockDim.x + threadIdx.x;
    if (e >= N_EDGES) return;
    int f64 = g_i64;
    int src = load_idx(ei, e, f64);
    int dst = load_idx(ei, (long long)N_EDGES + e, f64);
    float2 pp = ((const float2*)ea)[e];
    uint4 r;
    r.x = (unsigned)src;
    r.y = (unsigned)dst;
    r.z = __float_as_uint(pp.x);
    r.w = __float_as_uint(pp.y);
    g_erec[e] = r;
    atomicAdd(&g_cnt[dst], 1.f);
}

// ---------------- Z1 = x @ W1_k  (per node: 3 -> 4x16, fp16 out) -----------
__global__ __launch_bounds__(256) void k_z1(const float* __restrict__ x,
                                            const float* __restrict__ W1) {
    __shared__ float sW[192];   // W1[k][i][o] : k*48 + i*16 + o
    __shared__ float sx[64 * 3];
    int t = threadIdx.x;
    if (t < 192) sW[t] = W1[t];
    int base = blockIdx.x * 64;
    if (t < 192) {
        int idx = base * 3 + t;
        sx[t] = (idx < N_NODES * 3) ? x[idx] : 0.f;
    }
    __syncthreads();
    for (int e = t; e < 64 * 64; e += 256) {
        int ln = e >> 6;
        int n = base + ln;
        if (n >= N_NODES) continue;
        int j = e & 63;
        int k = j >> 4, o = j & 15;
        const float* w = sW + k * 48 + o;
        float s = sx[ln * 3 + 0] * w[0] + sx[ln * 3 + 1] * w[16] + sx[ln * 3 + 2] * w[32];
        g_Z1h[(size_t)n * 64 + j] = __float2half(s);
    }
}

// ---------------- layer1 edge scatter: 4 lanes per edge ---------------------
__global__ __launch_bounds__(256) void k_sc1() {
    int warpId = (blockIdx.x * 256 + threadIdx.x) >> 5;
    int lane = threadIdx.x & 31;
    int grp = lane >> 2, q = lane & 3;        // 8 edges per warp
    long long e = (long long)warpId * 8 + grp;
    if (e >= N_EDGES) return;
    uint4 r = g_erec[e];                      // broadcast within group
    int src = (int)r.x, dst = (int)r.y;
    float p0 = __uint_as_float(r.z), p1 = __uint_as_float(r.w);
    float q0 = 1.f - p0, q1 = 1.f - p1;
    float b0 = q1 * q0, b1 = q1 * p0, b2 = p1 * q0, b3 = p1 * p0;
    // Z1 row: 64 halfs = 16 uint2; k-chunk = 4 uint2; lane q takes uint2 (k*4+q)
    const uint2* zb = (const uint2*)(g_Z1h + (size_t)src * 64);
    uint2 z0 = zb[q], z1 = zb[4 + q], z2 = zb[8 + q], z3 = zb[12 + q];
    float4 a = h4f(z0), b = h4f(z1), c = h4f(z2), d = h4f(z3);
    float4 m;
    m.x = b0 * a.x + b1 * b.x + b2 * c.x + b3 * d.x;
    m.y = b0 * a.y + b1 * b.y + b2 * c.y + b3 * d.y;
    m.z = b0 * a.z + b1 * b.z + b2 * c.z + b3 * d.z;
    m.w = b0 * a.w + b1 * b.w + b2 * c.w + b3 * d.w;
    red4(g_agg1 + (size_t)dst * 16 + 4 * q, m);
}

// ---------------- layer1 finalize: mean-div + ELU + BN stats ---------------
__global__ __launch_bounds__(256) void k_fin1() {
    int T = gridDim.x * blockDim.x;
    int tid = blockIdx.x * blockDim.x + threadIdx.x;
    float sum = 0.f, sq = 0.f;
    for (int idx = tid; idx < N_NODES * 16; idx += T) {
        int n = idx >> 4;
        float c = fmaxf(g_cnt[n], 1.f);
        float h = elu1(g_agg1[idx] / c);
        g_agg1[idx] = h;
        sum += h; sq += h * h;
    }
    __shared__ float ss[32];
    if (threadIdx.x < 32) ss[threadIdx.x] = 0.f;
    __syncthreads();
    int ch = tid & 15;
    atomicAdd(&ss[ch], sum);
    atomicAdd(&ss[16 + ch], sq);
    __syncthreads();
    if (threadIdx.x < 32) atomicAdd(&g_stats1[threadIdx.x], ss[threadIdx.x]);
}

__global__ void k_bnp1(const float* __restrict__ gam, const float* __restrict__ bet) {
    int i = threadIdx.x;  // < 16
    float mu = g_stats1[i] * (1.f / N_NODES);
    float var = g_stats1[16 + i] * (1.f / N_NODES) - mu * mu;
    float A = rsqrtf(var + 1e-5f) * gam[i];
    g_bn1[i] = A;
    g_bn1[16 + i] = bet[i] - mu * A;
}

// ---------------- Z2 = bn(h1) @ W2_k  (16 -> 4x32, fp16 out) ----------------
__global__ __launch_bounds__(256) void k_z2(const float* __restrict__ W2) {
    __shared__ float sW[2048];   // W2[k][i][o] : k*512 + i*32 + o
    __shared__ float sh[64 * 16];
    int t = threadIdx.x;
    for (int i = t; i < 2048; i += 256) sW[i] = W2[i];
    int base = blockIdx.x * 64;
    for (int i = t; i < 1024; i += 256) {
        int n = base + (i >> 4);
        int ch = i & 15;
        float h = (n < N_NODES) ? g_agg1[(size_t)n * 16 + ch] : 0.f;
        sh[i] = h * g_bn1[ch] + g_bn1[16 + ch];
    }
    __syncthreads();
    for (int e = t; e < 64 * 128; e += 256) {
        int ln = e >> 7;
        int n = base + ln;
        if (n >= N_NODES) continue;
        int j = e & 127;
        int k = j >> 5, o = j & 31;
        const float* w = sW + k * 512 + o;
        const float* hh = sh + ln * 16;
        float s = 0.f;
#pragma unroll
        for (int i = 0; i < 16; i++) s += hh[i] * w[i * 32];
        g_Z2h[(size_t)n * 128 + j] = __float2half(s);
    }
}

// ---------------- layer2 edge scatter: 8 lanes per edge ---------------------
__global__ __launch_bounds__(256) void k_sc2() {
    int warpId = (blockIdx.x * 256 + threadIdx.x) >> 5;
    int lane = threadIdx.x & 31;
    int octet = lane >> 3, q = lane & 7;      // 4 edges per warp
    long long e = (long long)warpId * 4 + octet;
    if (e >= N_EDGES) return;
    uint4 r = g_erec[e];                      // broadcast within octet
    int src = (int)r.x, dst = (int)r.y;
    float p0 = __uint_as_float(r.z), p1 = __uint_as_float(r.w);
    float q0 = 1.f - p0, q1 = 1.f - p1;
    float b0 = q1 * q0, b1 = q1 * p0, b2 = p1 * q0, b3 = p1 * p0;
    // Z2 row: 128 halfs = 32 uint2; k-chunk = 8 uint2; lane q takes uint2 (k*8+q)
    const uint2* zb = (const uint2*)(g_Z2h + (size_t)src * 128);
    uint2 z0 = zb[q], z1 = zb[8 + q], z2 = zb[16 + q], z3 = zb[24 + q];
    float4 a = h4f(z0), b = h4f(z1), c = h4f(z2), d = h4f(z3);
    float4 m;
    m.x = b0 * a.x + b1 * b.x + b2 * c.x + b3 * d.x;
    m.y = b0 * a.y + b1 * b.y + b2 * c.y + b3 * d.y;
    m.z = b0 * a.z + b1 * b.z + b2 * c.z + b3 * d.z;
    m.w = b0 * a.w + b1 * b.w + b2 * c.w + b3 * d.w;
    red4(g_agg2 + (size_t)dst * 32 + 4 * q, m);
}

// ---------------- layer2 finalize ------------------------------------------
__global__ __launch_bounds__(256) void k_fin2() {
    int T = gridDim.x * blockDim.x;
    int tid = blockIdx.x * blockDim.x + threadIdx.x;
    float sum = 0.f, sq = 0.f;
    for (int idx = tid; idx < N_NODES * 32; idx += T) {
        int n = idx >> 5;
        float c = fmaxf(g_cnt[n], 1.f);
        float h = elu1(g_agg2[idx] / c);
        g_agg2[idx] = h;
        sum += h; sq += h * h;
    }
    __shared__ float ss[64];
    if (threadIdx.x < 64) ss[threadIdx.x] = 0.f;
    __syncthreads();
    int ch = tid & 31;
    atomicAdd(&ss[ch], sum);
    atomicAdd(&ss[32 + ch], sq);
    __syncthreads();
    if (threadIdx.x < 64) atomicAdd(&g_stats2[threadIdx.x], ss[threadIdx.x]);
}

__global__ void k_bnp2(const float* __restrict__ gam, const float* __restrict__ bet) {
    int i = threadIdx.x;  // < 32
    float mu = g_stats2[i] * (1.f / N_NODES);
    float var = g_stats2[32 + i] * (1.f / N_NODES) - mu * mu;
    float A = rsqrtf(var + 1e-5f) * gam[i];
    g_bn2[i] = A;
    g_bn2[32 + i] = bet[i] - mu * A;
}

// ---------------- graph mean pool (batch is sorted) -------------------------
__global__ __launch_bounds__(256) void k_pool(const void* __restrict__ batch) {
    __shared__ float sg[N_GRAPHS * 32];
    __shared__ float sc[N_GRAPHS];
    int t = threadIdx.x;
    for (int i = t; i < N_GRAPHS * 32; i += 256) sg[i] = 0.f;
    if (t < N_GRAPHS) sc[t] = 0.f;
    __syncthreads();
    int f64 = g_i64;
    int lane = t & 31, warp = t >> 5;
    const int NPW = 256;
    int gw = blockIdx.x * 8 + warp;
    int start = gw * NPW;
    int end = min(start + NPW, N_NODES);
    float A = g_bn2[lane], B = g_bn2[32 + lane];
    float acc = 0.f, cacc = 0.f;
    int curg = -1;
    for (int n = start; n < end; n++) {
        int g = load_idx(batch, n, f64);
        if (g != curg) {
            if (curg >= 0) {
                atomicAdd(&sg[curg * 32 + lane], acc);
                if (lane == 0) atomicAdd(&sc[curg], cacc);
            }
            curg = g; acc = 0.f; cacc = 0.f;
        }
        float h = g_agg2[(size_t)n * 32 + lane];
        acc += h * A + B;
        cacc += 1.f;
    }
    if (curg >= 0) {
        atomicAdd(&sg[curg * 32 + lane], acc);
        if (lane == 0) atomicAdd(&sc[curg], cacc);
    }
    __syncthreads();
    for (int i = t; i < N_GRAPHS * 32; i += 256)
        if (sg[i] != 0.f) atomicAdd(&g_gsum[i], sg[i]);
    if (t < N_GRAPHS && sc[t] != 0.f) atomicAdd(&g_gcnt[t], sc[t]);
}

// ---------------- final: gm @ fc_w^T ----------------------------------------
__global__ void k_final(const float* __restrict__ fc, float* __restrict__ out) {
    int t = threadIdx.x;
    if (t >= N_GRAPHS * 10) return;
    int g = t / 10, c = t % 10;
    float cg = fmaxf(g_gcnt[g], 1.f);
    float inv = 1.f / cg;
    float s = 0.f;
#pragma unroll
    for (int i = 0; i < 32; i++) s += (g_gsum[g * 32 + i] * inv) * fc[c * 32 + i];
    out[g * 10 + c] = s;
}

// ---------------- launch -----------------------------------------------------
extern "C" void kernel_launch(void* const* d_in, const int* in_sizes, int n_in,
                              void* d_out, int out_size) {
    const float* x     = (const float*)d_in[0];
    const void*  ei    = d_in[1];
    const float* ea    = (const float*)d_in[2];
    const void*  batch = d_in[3];
    const float* W1    = (const float*)d_in[4];
    const float* g1    = (const float*)d_in[5];
    const float* b1    = (const float*)d_in[6];
    const float* W2    = (const float*)d_in[7];
    const float* g2    = (const float*)d_in[8];
    const float* b2    = (const float*)d_in[9];
    const float* fc    = (const float*)d_in[10];
    float* out = (float*)d_out;

    void* p;
    cudaGetSymbolAddress(&p, g_agg1);   cudaMemsetAsync(p, 0, sizeof(g_agg1));
    cudaGetSymbolAddress(&p, g_agg2);   cudaMemsetAsync(p, 0, sizeof(g_agg2));
    cudaGetSymbolAddress(&p, g_cnt);    cudaMemsetAsync(p, 0, sizeof(g_cnt));
    cudaGetSymbolAddress(&p, g_stats1); cudaMemsetAsync(p, 0, sizeof(g_stats1));
    cudaGetSymbolAddress(&p, g_stats2); cudaMemsetAsync(p, 0, sizeof(g_stats2));
    cudaGetSymbolAddress(&p, g_gsum);   cudaMemsetAsync(p, 0, sizeof(g_gsum));
    cudaGetSymbolAddress(&p, g_gcnt);   cudaMemsetAsync(p, 0, sizeof(g_gcnt));

    int nodeBlocks = (N_NODES + 63) / 64;

    k_detect<<<1, 1>>>((const int*)ei);
    k_prep<<<(N_EDGES + 255) / 256, 256>>>(ei, ea);
    k_z1<<<nodeBlocks, 256>>>(x, W1);
    // sc1: 8 edges/warp, 8 warps/block -> 64 edges per block
    k_sc1<<<N_EDGES / 64, 256>>>();
    k_fin1<<<592, 256>>>();
    k_bnp1<<<1, 16>>>(g1, b1);
    k_z2<<<nodeBlocks, 256>>>(W2);
    // sc2: 4 edges/warp, 8 warps/block -> 32 edges per block
    k_sc2<<<N_EDGES / 32, 256>>>();
    k_fin2<<<592, 256>>>();
    k_bnp2<<<1, 32>>>(g2, b2);
    k_pool<<<(N_NODES + 8 * 256 - 1) / (8 * 256), 256>>>(batch);
    k_final<<<1, N_GRAPHS * 10>>>(fc, out);
}